// round 17
// baseline (speedup 1.0000x reference)
#include <cuda_runtime.h>
#include <cstdint>

// Correlation (FlowNet, MAX_DISP=4) via mma.sync tf32 band-GEMM.
// first/second: (4,256,128,224) f32 NCHW; out: (4,81,128,224) f32.
// Per CTA: M=64 first-pixels (8y x 8x), N=256 second-window pixels (16x16),
// K=256 channels. D[m,n] = sum_k F[k,m]*S[k,n], register accumulators.
// out[b, dy*9+dx, y0+ly, x0+lx] = D[ly*8+lx, (ly+dy)*16 + lx+dx] / 256.

#define B_ 4
#define C_ 256
#define H_ 128
#define W_ 224
#define HW_ 28672
#define ND_ 81

#define TY 8
#define TXW 8
#define M_ 64
#define WR 16      // window rows
#define WC 16      // window cols
#define N_ 256
#define KC 32      // K per chunk
#define NKCH 8

#define SSTR 36    // smem row stride (floats): LDS.32 frags + STS conflict-free
#define AB_F (M_ * SSTR)          // 2304 floats
#define BB_F (N_ * SSTR)          // 9216 floats
#define OFF_A0 0
#define OFF_A1 AB_F
#define OFF_B0 (2 * AB_F)         // 4608
#define OFF_B1 (2 * AB_F + BB_F)  // 13824
#define SMEM_FLOATS (2 * AB_F + 2 * BB_F)   // 23040
#define SMEM_TOTAL (SMEM_FLOATS * 4)        // 92160 B

#define SD 264     // epilogue stage stride (floats); 64*264=16896 <= 23040

#define NTHR 256
#define NSLOT 2560 // per chunk: 512 A quads + 2048 B quads = exactly 10*256

__device__ __forceinline__ uint32_t smem_u32(const void* p) {
    return (uint32_t)__cvta_generic_to_shared(p);
}
__device__ __forceinline__ void cp4(uint32_t dst, const float* src, int sz) {
    asm volatile("cp.async.ca.shared.global [%0], [%1], 4, %2;\n"
                 :: "r"(dst), "l"(src), "r"(sz));
}
__device__ __forceinline__ void cp_commit() {
    asm volatile("cp.async.commit_group;\n");
}
__device__ __forceinline__ void cp_wait_all() {
    asm volatile("cp.async.wait_group 0;\n");
}
__device__ __forceinline__ uint32_t f2tf(float f) {
    uint32_t u;
    asm("cvt.rna.tf32.f32 %0, %1;" : "=r"(u) : "f"(f));
    return u;
}
__device__ __forceinline__ void mma_tf32(float* d,
                                         uint32_t a0, uint32_t a1,
                                         uint32_t a2, uint32_t a3,
                                         uint32_t b0, uint32_t b1) {
    asm volatile(
        "mma.sync.aligned.m16n8k8.row.col.f32.tf32.tf32.f32 "
        "{%0,%1,%2,%3}, {%4,%5,%6,%7}, {%8,%9}, {%0,%1,%2,%3};"
        : "+f"(d[0]), "+f"(d[1]), "+f"(d[2]), "+f"(d[3])
        : "r"(a0), "r"(a1), "r"(a2), "r"(a3), "r"(b0), "r"(b1));
}

__global__ __launch_bounds__(NTHR, 2)
void corr_kernel(const float* __restrict__ first,
                 const float* __restrict__ second,
                 float* __restrict__ out)
{
    extern __shared__ __align__(16) float dyn[];
    const uint32_t smem_base = smem_u32(dyn);

    const int x0 = blockIdx.x * TXW;    // 0..216
    const int y0 = blockIdx.y * TY;     // 0..120
    const int b  = blockIdx.z;

    const int tid  = threadIdx.x;
    const int warp = tid >> 5;
    const int lane = tid & 31;
    const int s    = warp >> 1;         // M strip (rows 16s..16s+15)
    const int nh   = warp & 1;          // N half (cols 128*nh..)
    const int g    = lane >> 2;         // group id 0..7
    const int tig  = lane & 3;          // thread in group 0..3

    const float* fB = first  + (size_t)b * C_ * HW_;
    const float* sB = second + (size_t)b * C_ * HW_;

    // ---------- fill helper (per chunk kc into buffer kc&1) ----------
    auto fill = [&](int kc) {
        const int cbase = kc * KC;
        const uint32_t aoff = (kc & 1) ? OFF_A1 : OFF_A0;
        const uint32_t boff = (kc & 1) ? OFF_B1 : OFF_B0;
#pragma unroll
        for (int it = 0; it < 10; it++) {
            const int idx = tid + it * NTHR;       // 0..2559
            uint32_t dst;
            const float* src;
            int sz = 4;
            if (idx < 512) {                       // A quad: q=idx>>6, pix=idx&63
                const int q = idx >> 6, pix = idx & 63;
                const int gy = y0 + (pix >> 3), gx = x0 + (pix & 7);
                src = fB + ((size_t)(cbase + 4 * q) * HW_ + gy * W_ + gx);
                dst = smem_base + (aoff + pix * SSTR + 4 * q) * 4;
            } else {                               // B quad
                const int i2 = idx - 512;
                const int q = i2 >> 8, pix = i2 & 255;
                const int gy = y0 - 4 + (pix >> 4), gx = x0 - 4 + (pix & 15);
                const bool ok = ((unsigned)gy < (unsigned)H_) &&
                                ((unsigned)gx < (unsigned)W_);
                src = sB + ((size_t)(cbase + 4 * q) * HW_ + (ok ? gy * W_ + gx : 0));
                sz = ok ? 4 : 0;
                dst = smem_base + (boff + pix * SSTR + 4 * q) * 4;
            }
#pragma unroll
            for (int j = 0; j < 4; j++)
                cp4(dst + j * 4, src + (size_t)j * HW_, sz);
        }
        cp_commit();
    };

    // accumulators: 16 n-tiles x 4 regs
    float acc[16][4];
#pragma unroll
    for (int nt = 0; nt < 16; nt++)
#pragma unroll
        for (int i = 0; i < 4; i++)
            acc[nt][i] = 0.0f;

    fill(0);

    for (int kc = 0; kc < NKCH; kc++) {
        cp_wait_all();        // chunk kc resident (only its group pending)
        __syncthreads();      // all threads past compute(kc-1); data visible
        if (kc + 1 < NKCH)
            fill(kc + 1);     // async into other buffer, overlaps compute

        const float* ab = dyn + ((kc & 1) ? OFF_A1 : OFF_A0);
        const float* bb = dyn + ((kc & 1) ? OFF_B1 : OFF_B0);
        const float* arow  = ab + (16 * s + g) * SSTR;
        const float* brow0 = bb + (128 * nh + g) * SSTR;

#pragma unroll
        for (int st = 0; st < 4; st++) {
            const int ko = st * 8 + tig;
            const uint32_t a0 = f2tf(arow[ko]);
            const uint32_t a1 = f2tf(arow[8 * SSTR + ko]);
            const uint32_t a2 = f2tf(arow[ko + 4]);
            const uint32_t a3 = f2tf(arow[8 * SSTR + ko + 4]);
#pragma unroll
            for (int nt = 0; nt < 16; nt++) {
                const float* bp = brow0 + nt * 8 * SSTR + ko;
                const uint32_t b0 = f2tf(bp[0]);
                const uint32_t b1 = f2tf(bp[4]);
                mma_tf32(acc[nt], a0, a1, a2, a3, b0, b1);
            }
        }
    }

    __syncthreads();   // all compute done before staging over the buffers

    // ---------- stage D[64][256] into smem (stride SD) ----------
    float* stg = dyn;
    {
        float* r0 = stg + (16 * s + g) * SD + 128 * nh + 2 * tig;
        float* r1 = r0 + 8 * SD;
#pragma unroll
        for (int nt = 0; nt < 16; nt++) {
            *(float2*)(r0 + nt * 8) = make_float2(acc[nt][0], acc[nt][1]);
            *(float2*)(r1 + nt * 8) = make_float2(acc[nt][2], acc[nt][3]);
        }
    }
    __syncthreads();

    // ---------- write out: 81 channels x 64 pixels ----------
    const float scale = 1.0f / (float)C_;
    const int pix = tid & 63, qtr = tid >> 6;
    const int ly = pix >> 3, lx = pix & 7;
    const float* dp = stg + pix * SD;
    for (int ch = qtr; ch < ND_; ch += 4) {
        const int dy = (ch * 57) >> 9;      // == ch/9 for ch<81
        const int dx = ch - dy * 9;
        const int n = (ly + dy) * WC + lx + dx;
        out[((size_t)(b * ND_ + ch) * H_ + y0 + ly) * W_ + x0 + lx] = dp[n] * scale;
    }
}

extern "C" void kernel_launch(void* const* d_in, const int* in_sizes, int n_in,
                              void* d_out, int out_size)
{
    const float* first  = (const float*)d_in[0];
    const float* second = (const float*)d_in[1];
    float* out = (float*)d_out;

    cudaFuncSetAttribute(corr_kernel,
                         cudaFuncAttributeMaxDynamicSharedMemorySize, SMEM_TOTAL);

    dim3 grid(W_ / TXW, H_ / TY, B_);   // (28, 16, 4) = 1792 CTAs
    dim3 block(NTHR);                   // 256
    corr_kernel<<<grid, block, SMEM_TOTAL>>>(first, second, out);
}